// round 7
// baseline (speedup 1.0000x reference)
#include <cuda_runtime.h>

// Problem constants
#define NPTS    131072
#define DIM     128
#define NBOOK   4
#define KCODES  1024
#define NCODES  4096

#define THREADS 256
#define SMEM_MAIN (2 * 65536)

__device__ float g_csq[NCODES];

// 8-byte-granular swizzle: XOR byte-addr bits [6:3] with row bits [6:3].
// b-loads (rows tx*8+j, 16 distinct tx): bank-group = (k2^tx)&15 -> bijective,
// conflict-free. a-loads: 2 distinct rows/warp -> broadcast. 16B stores stay
// 16B-aligned per 8B-half (we store as two float2).
__device__ __forceinline__ unsigned swzb(unsigned row, unsigned kb) {
    return row * 512u + (kb ^ (((row >> 3) & 15u) << 3));
}

__device__ __forceinline__ void ffma2(unsigned long long& d,
                                      unsigned long long a,
                                      unsigned long long b) {
    asm("fma.rn.f32x2 %0, %1, %2, %0;" : "+l"(d) : "l"(a), "l"(b));
}

__device__ __forceinline__ float u64_lo(unsigned long long v) {
    return __uint_as_float((unsigned)(v & 0xffffffffull));
}
__device__ __forceinline__ float u64_hi(unsigned long long v) {
    return __uint_as_float((unsigned)(v >> 32));
}

// (val, idx) argmin with lowest-index tie-break (matches jnp.argmin).
__device__ __forceinline__ void amin2(float& v, int& i, float ov, int oi) {
    if (ov < v || (ov == v && oi < i)) { v = ov; i = oi; }
}

// ||c||^2 for all 4096 codes. One warp per code.
__global__ void csq_kernel(const float* __restrict__ cb) {
    int warp = threadIdx.x >> 5;
    int lane = threadIdx.x & 31;
    int code = blockIdx.x * 8 + warp;
    float4 v = reinterpret_cast<const float4*>(cb)[code * 32 + lane];
    float s = v.x * v.x + v.y * v.y + v.z * v.z + v.w * v.w;
#pragma unroll
    for (int o = 16; o > 0; o >>= 1) s += __shfl_xor_sync(0xffffffffu, s, o);
    if (lane == 0) g_csq[code] = s;
}

extern __shared__ char smem[];

__global__ void __launch_bounds__(THREADS, 1)
rqk_kernel(const float* __restrict__ x, const float* __restrict__ cb,
           float* __restrict__ out) {
    char* xs = smem;
    char* cs = smem + 65536;

    const int tid  = threadIdx.x;
    const int lane = tid & 31;
    const int warp = tid >> 5;
    const int tx   = lane & 15;               // code group (8 codes)
    const int ty   = warp * 2 + (lane >> 4);  // row group (8 rows), 0..15
    const int row0 = blockIdx.x * 128;

    // ---- load x tile [128 x 128] into swizzled shared ----
    {
        const float4* x4 = reinterpret_cast<const float4*>(x) + (size_t)row0 * 32;
#pragma unroll
        for (int it = 0; it < 16; ++it) {
            int idx = it * 256 + tid;
            int r = idx >> 5, c4 = idx & 31;
            float4 v = x4[r * 32 + c4];
            *reinterpret_cast<float2*>(xs + swzb(r, c4 * 16))     = make_float2(v.x, v.y);
            *reinterpret_cast<float2*>(xs + swzb(r, c4 * 16 + 8)) = make_float2(v.z, v.w);
        }
    }

    const float4* cb4 = reinterpret_cast<const float4*>(cb);
    float best_v[8];
    int   best_i[8];

    for (int t = 0; t < 32; ++t) {
        __syncthreads();
        // ---- load code tile [128 x 128] into swizzled shared ----
#pragma unroll
        for (int it = 0; it < 16; ++it) {
            int idx = it * 256 + tid;
            int r = idx >> 5, c4 = idx & 31;
            float4 v = cb4[((size_t)t * 128 + r) * 32 + c4];
            *reinterpret_cast<float2*>(cs + swzb(r, c4 * 16))     = make_float2(v.x, v.y);
            *reinterpret_cast<float2*>(cs + swzb(r, c4 * 16 + 8)) = make_float2(v.z, v.w);
        }
        __syncthreads();

        if ((t & 7) == 0) {
#pragma unroll
            for (int i = 0; i < 8; ++i) { best_v[i] = 3.4e38f; best_i[i] = 0; }
        }

        // ---- 8x8 micro-tile, k packed in f32x2 pairs ----
        unsigned long long acc[8][8];
#pragma unroll
        for (int i = 0; i < 8; ++i)
#pragma unroll
            for (int j = 0; j < 8; ++j) acc[i][j] = 0ull;

#pragma unroll 4
        for (int k2 = 0; k2 < 64; ++k2) {
            unsigned long long a[8], b[8];
#pragma unroll
            for (int i = 0; i < 8; ++i)
                a[i] = *reinterpret_cast<const unsigned long long*>(
                    xs + swzb(ty * 8 + i, k2 * 8));
#pragma unroll
            for (int j = 0; j < 8; ++j)
                b[j] = *reinterpret_cast<const unsigned long long*>(
                    cs + swzb(tx * 8 + j, k2 * 8));
#pragma unroll
            for (int i = 0; i < 8; ++i)
#pragma unroll
                for (int j = 0; j < 8; ++j) ffma2(acc[i][j], a[i], b[j]);
        }

        // ---- score = csq - 2*dot, running per-row argmin ----
        float csq_r[8];
#pragma unroll
        for (int j = 0; j < 8; ++j) csq_r[j] = g_csq[t * 128 + tx * 8 + j];

#pragma unroll
        for (int i = 0; i < 8; ++i)
#pragma unroll
            for (int j = 0; j < 8; ++j) {
                float dot = u64_lo(acc[i][j]) + u64_hi(acc[i][j]);
                float s = fmaf(-2.0f, dot, csq_r[j]);
                int cid = ((t & 7) << 7) + (tx << 3) + j;
                amin2(best_v[i], best_i[i], s, cid);
            }

        // ---- end of book: argmin across 16 tx-lanes, store as float ----
        if ((t & 7) == 7) {
#pragma unroll
            for (int i = 0; i < 8; ++i) {
                float v  = best_v[i];
                int   bi = best_i[i];
#pragma unroll
                for (int off = 1; off < 16; off <<= 1) {
                    float ov = __shfl_xor_sync(0xffffffffu, v, off);
                    int   oi = __shfl_xor_sync(0xffffffffu, bi, off);
                    amin2(v, bi, ov, oi);
                }
                if (tx == 0)
                    out[(size_t)(row0 + ty * 8 + i) * NBOOK + (t >> 3)] =
                        (float)bi;   // output dtype is float32
            }
        }
    }
}

extern "C" void kernel_launch(void* const* d_in, const int* in_sizes, int n_in,
                              void* d_out, int out_size) {
    const float* x  = nullptr;
    const float* cb = nullptr;
    for (int i = 0; i < n_in; ++i) {
        long long s = in_sizes[i];
        if (s == 16777216LL || s == 67108864LL) x  = (const float*)d_in[i];
        if (s == 524288LL   || s == 2097152LL)  cb = (const float*)d_in[i];
    }
    if (!x)  x  = (const float*)d_in[0];
    if (!cb) cb = (const float*)d_in[n_in > 1 ? 1 : 0];

    csq_kernel<<<NCODES / 8, 256>>>(cb);

    cudaFuncSetAttribute(rqk_kernel, cudaFuncAttributeMaxDynamicSharedMemorySize,
                         SMEM_MAIN);
    rqk_kernel<<<NPTS / 128, THREADS, SMEM_MAIN>>>(x, cb, (float*)d_out);
}

// round 8
// speedup vs baseline: 1.2534x; 1.2534x over previous
#include <cuda_runtime.h>

// Problem constants
#define NPTS    131072
#define DIM     128
#define NBOOK   4
#define KCODES  1024
#define NCODES  4096

#define THREADS 256
// smem: xs 64KB | cs buf0 64KB | cs buf1 64KB
#define XS_OFF  0
#define CS_OFF  65536
#define SMEM_MAIN (3 * 65536)

__device__ float g_csq[NCODES];

// 16-byte-granular swizzle: XOR byte-address bits [6:4] with (row>>3)&7.
// Same function for store and load -> self-consistent.
__device__ __forceinline__ unsigned swz(unsigned row, unsigned kb) {
    return row * 512u + (kb ^ (((row >> 3) & 7u) << 4));
}

// (val, idx) argmin with lowest-index tie-break (matches jnp.argmin).
__device__ __forceinline__ void amin2(float& v, int& i, float ov, int oi) {
    if (ov < v || (ov == v && oi < i)) { v = ov; i = oi; }
}

__device__ __forceinline__ unsigned smem_u32(const void* p) {
    return (unsigned)__cvta_generic_to_shared(p);
}

__device__ __forceinline__ void cp16(unsigned dst_smem, const void* src) {
    asm volatile("cp.async.cg.shared.global [%0], [%1], 16;"
                 :: "r"(dst_smem), "l"(src));
}
__device__ __forceinline__ void cp_commit() {
    asm volatile("cp.async.commit_group;");
}
__device__ __forceinline__ void cp_wait_all() {
    asm volatile("cp.async.wait_group 0;");
}

// ||c||^2 for all 4096 codes. One warp per code.
__global__ void csq_kernel(const float* __restrict__ cb) {
    int warp = threadIdx.x >> 5;
    int lane = threadIdx.x & 31;
    int code = blockIdx.x * 8 + warp;
    float4 v = reinterpret_cast<const float4*>(cb)[code * 32 + lane];
    float s = v.x * v.x + v.y * v.y + v.z * v.z + v.w * v.w;
#pragma unroll
    for (int o = 16; o > 0; o >>= 1) s += __shfl_xor_sync(0xffffffffu, s, o);
    if (lane == 0) g_csq[code] = s;
}

extern __shared__ char smem[];

__global__ void __launch_bounds__(THREADS, 1)
rqk_kernel(const float* __restrict__ x, const float* __restrict__ cb,
           float* __restrict__ out) {
    char* xs = smem + XS_OFF;

    const int tid  = threadIdx.x;
    const int lane = tid & 31;
    const int warp = tid >> 5;
    const int tx   = lane & 15;               // code group (8 codes)
    const int ty   = warp * 2 + (lane >> 4);  // row group (8 rows), 0..15
    const int row0 = blockIdx.x * 128;

    // Per-thread fixed (row, col4) slots for tile loading: 16 slots.
    const int ld_r0 = tid >> 5;     // rows tid>>5, +8, +16, ... (step 8)
    const int ld_c4 = tid & 31;     // float4 column

    // ---- load x tile [128 x 128] (plain, once) ----
    {
        const float4* x4 = reinterpret_cast<const float4*>(x) + (size_t)row0 * 32;
#pragma unroll
        for (int it = 0; it < 16; ++it) {
            int r = ld_r0 + it * 8;
            *reinterpret_cast<float4*>(xs + swz(r, ld_c4 * 16)) = x4[r * 32 + ld_c4];
        }
    }

    const float4* cb4 = reinterpret_cast<const float4*>(cb);

    // ---- prefetch code tile 0 into cs buffer 0 ----
    {
        char* cs = smem + CS_OFF;
#pragma unroll
        for (int it = 0; it < 16; ++it) {
            int r = ld_r0 + it * 8;
            cp16(smem_u32(cs + swz(r, ld_c4 * 16)), &cb4[(size_t)r * 32 + ld_c4]);
        }
        cp_commit();
    }

    float best_v[8];
    int   best_i[8];

    for (int t = 0; t < 32; ++t) {
        cp_wait_all();
        __syncthreads();   // tile t ready in buf (t&1); everyone done with buf (1-t&1)

        // ---- prefetch tile t+1 into the other buffer ----
        if (t + 1 < 32) {
            char* csn = smem + CS_OFF + ((t + 1) & 1) * 65536;
#pragma unroll
            for (int it = 0; it < 16; ++it) {
                int r = ld_r0 + it * 8;
                cp16(smem_u32(csn + swz(r, ld_c4 * 16)),
                     &cb4[((size_t)(t + 1) * 128 + r) * 32 + ld_c4]);
            }
            cp_commit();
        }

        char* cs = smem + CS_OFF + (t & 1) * 65536;

        if ((t & 7) == 0) {
#pragma unroll
            for (int i = 0; i < 8; ++i) { best_v[i] = 3.4e38f; best_i[i] = 0; }
        }

        // ---- 8x8 micro-tile dots (scalar FFMA) ----
        float acc[8][8];
#pragma unroll
        for (int i = 0; i < 8; ++i)
#pragma unroll
            for (int j = 0; j < 8; ++j) acc[i][j] = 0.0f;

#pragma unroll 2
        for (int k4 = 0; k4 < 32; ++k4) {
            float4 a[8], b[8];
#pragma unroll
            for (int i = 0; i < 8; ++i)
                a[i] = *reinterpret_cast<const float4*>(xs + swz(ty * 8 + i, k4 * 16));
#pragma unroll
            for (int j = 0; j < 8; ++j)
                b[j] = *reinterpret_cast<const float4*>(cs + swz(tx * 8 + j, k4 * 16));
#pragma unroll
            for (int i = 0; i < 8; ++i)
#pragma unroll
                for (int j = 0; j < 8; ++j) {
                    acc[i][j] = fmaf(a[i].x, b[j].x, acc[i][j]);
                    acc[i][j] = fmaf(a[i].y, b[j].y, acc[i][j]);
                    acc[i][j] = fmaf(a[i].z, b[j].z, acc[i][j]);
                    acc[i][j] = fmaf(a[i].w, b[j].w, acc[i][j]);
                }
        }

        // ---- score = csq - 2*dot, running per-row argmin ----
        float csq_r[8];
#pragma unroll
        for (int j = 0; j < 8; ++j) csq_r[j] = g_csq[t * 128 + tx * 8 + j];

#pragma unroll
        for (int i = 0; i < 8; ++i)
#pragma unroll
            for (int j = 0; j < 8; ++j) {
                float s = fmaf(-2.0f, acc[i][j], csq_r[j]);
                int cid = ((t & 7) << 7) + (tx << 3) + j;
                amin2(best_v[i], best_i[i], s, cid);
            }

        // ---- end of book: argmin across 16 tx-lanes, store as float ----
        if ((t & 7) == 7) {
#pragma unroll
            for (int i = 0; i < 8; ++i) {
                float v  = best_v[i];
                int   bi = best_i[i];
#pragma unroll
                for (int off = 1; off < 16; off <<= 1) {
                    float ov = __shfl_xor_sync(0xffffffffu, v, off);
                    int   oi = __shfl_xor_sync(0xffffffffu, bi, off);
                    amin2(v, bi, ov, oi);
                }
                if (tx == 0)
                    out[(size_t)(row0 + ty * 8 + i) * NBOOK + (t >> 3)] =
                        (float)bi;   // output dtype is float32
            }
        }
        __syncthreads();   // all reads of buf (t&1) done before next prefetch cycle
    }
}

extern "C" void kernel_launch(void* const* d_in, const int* in_sizes, int n_in,
                              void* d_out, int out_size) {
    const float* x  = nullptr;
    const float* cb = nullptr;
    for (int i = 0; i < n_in; ++i) {
        long long s = in_sizes[i];
        if (s == 16777216LL || s == 67108864LL) x  = (const float*)d_in[i];
        if (s == 524288LL   || s == 2097152LL)  cb = (const float*)d_in[i];
    }
    if (!x)  x  = (const float*)d_in[0];
    if (!cb) cb = (const float*)d_in[n_in > 1 ? 1 : 0];

    csq_kernel<<<NCODES / 8, 256>>>(cb);

    cudaFuncSetAttribute(rqk_kernel, cudaFuncAttributeMaxDynamicSharedMemorySize,
                         SMEM_MAIN);
    rqk_kernel<<<NPTS / 128, THREADS, SMEM_MAIN>>>(x, cb, (float*)d_out);
}